// round 3
// baseline (speedup 1.0000x reference)
#include <cuda_runtime.h>
#include <cuda_bf16.h>

// ============================================================================
// ECE over N=2^24 samples, 15 bins — single fused kernel.
//   bin(c) = ceil(c*nb) - 1  for c in (0,1], else dropped
//   ece    = sum_b | sum_{i in b} (conf_i - acc_i) | / n
//
// R3 change: __launch_bounds__(256, 4) -> 64 regs so the 8 front-batched
// LDG.128 actually stay in flight (R2's 32-reg cap serialized them; DRAM
// stuck at 57%). Grid 512 = one wave at occ 4; 32 vec4/thread, no tail.
// ============================================================================

#define TPB 256
#define MAX_BINS 16          // supports num_bins <= 16 (problem uses 15)
#define NBLOCKS 512          // 2^17 threads; single wave at 4 CTAs/SM
#define MAX_BLOCKS 4096

__device__ float g_partial[MAX_BLOCKS * MAX_BINS];
__device__ unsigned int g_count = 0;

__device__ __forceinline__ void bin_add(float* __restrict__ sb, int tid,
                                        float cf, float af, float fnb, int nbm1) {
    if (cf > 0.0f && cf <= 1.0f) {
        int b = __float2int_ru(cf * fnb) - 1;   // ceil(c*nb)-1, single F2I.RU
        b = max(0, min(b, nbm1));
        sb[b * TPB + tid] += cf - af;
    }
}

__global__ __launch_bounds__(TPB, 4)
void ece_kernel(const float* __restrict__ conf,
                const float* __restrict__ acc,
                const int* __restrict__ num_bins_p,
                int n,
                float* __restrict__ out) {
    __shared__ float sb[MAX_BINS * TPB];   // 16 KB, per-lane private bins
    const int tid = threadIdx.x;
    const int nb = *num_bins_p;
    const float fnb = (float)nb;
    const int nbm1 = nb - 1;

    #pragma unroll
    for (int b = 0; b < MAX_BINS; b++)
        sb[b * TPB + tid] = 0.0f;
    __syncthreads();

    const int nvec = n >> 2;
    const float4* __restrict__ c4 = (const float4*)conf;
    const float4* __restrict__ a4 = (const float4*)acc;
    const int T = gridDim.x * blockDim.x;

    int i = blockIdx.x * blockDim.x + tid;
    // 4x unrolled grid-stride: 8 front-batched LDG.128 per iteration.
    // With 64 regs available these all issue back-to-back (MLP_p1 = 8).
    for (; i + 3 * T < nvec; i += 4 * T) {
        const float4 c0 = __ldg(&c4[i]);
        const float4 c1 = __ldg(&c4[i + T]);
        const float4 c2 = __ldg(&c4[i + 2 * T]);
        const float4 c3 = __ldg(&c4[i + 3 * T]);
        const float4 a0 = __ldg(&a4[i]);
        const float4 a1 = __ldg(&a4[i + T]);
        const float4 a2 = __ldg(&a4[i + 2 * T]);
        const float4 a3 = __ldg(&a4[i + 3 * T]);
        bin_add(sb, tid, c0.x, a0.x, fnb, nbm1);
        bin_add(sb, tid, c0.y, a0.y, fnb, nbm1);
        bin_add(sb, tid, c0.z, a0.z, fnb, nbm1);
        bin_add(sb, tid, c0.w, a0.w, fnb, nbm1);
        bin_add(sb, tid, c1.x, a1.x, fnb, nbm1);
        bin_add(sb, tid, c1.y, a1.y, fnb, nbm1);
        bin_add(sb, tid, c1.z, a1.z, fnb, nbm1);
        bin_add(sb, tid, c1.w, a1.w, fnb, nbm1);
        bin_add(sb, tid, c2.x, a2.x, fnb, nbm1);
        bin_add(sb, tid, c2.y, a2.y, fnb, nbm1);
        bin_add(sb, tid, c2.z, a2.z, fnb, nbm1);
        bin_add(sb, tid, c2.w, a2.w, fnb, nbm1);
        bin_add(sb, tid, c3.x, a3.x, fnb, nbm1);
        bin_add(sb, tid, c3.y, a3.y, fnb, nbm1);
        bin_add(sb, tid, c3.z, a3.z, fnb, nbm1);
        bin_add(sb, tid, c3.w, a3.w, fnb, nbm1);
    }
    for (; i < nvec; i += T) {
        const float4 c = __ldg(&c4[i]);
        const float4 a = __ldg(&a4[i]);
        bin_add(sb, tid, c.x, a.x, fnb, nbm1);
        bin_add(sb, tid, c.y, a.y, fnb, nbm1);
        bin_add(sb, tid, c.z, a.z, fnb, nbm1);
        bin_add(sb, tid, c.w, a.w, fnb, nbm1);
    }
    // scalar remainder (n not multiple of 4): block 0 only
    if (blockIdx.x == 0) {
        for (int j = (nvec << 2) + tid; j < n; j += blockDim.x) {
            const float cf = conf[j];
            if (cf > 0.0f && cf <= 1.0f) {
                int b = __float2int_ru(cf * fnb) - 1;
                b = max(0, min(b, nbm1));
                sb[b * TPB + tid] += cf - acc[j];
            }
        }
    }
    __syncthreads();

    // tree-reduce the 256 per-lane copies (addr stride 4B -> conflict-free)
    for (int s = TPB / 2; s > 0; s >>= 1) {
        if (tid < s) {
            #pragma unroll
            for (int b = 0; b < MAX_BINS; b++)
                sb[b * TPB + tid] += sb[b * TPB + tid + s];
        }
        __syncthreads();
    }

    if (tid < MAX_BINS)
        g_partial[blockIdx.x * MAX_BINS + tid] = sb[tid * TPB];

    // ---- last-block tail reduction (no second launch) ----
    __shared__ bool is_last;
    __threadfence();
    if (tid == 0) {
        unsigned int ticket = atomicAdd(&g_count, 1u);
        is_last = (ticket == gridDim.x - 1);
    }
    __syncthreads();

    if (is_last) {
        __threadfence();
        // total = gridDim.x * 16; element e -> bin (e & 15). Stride 256 keeps
        // bin = tid & 15 constant per thread; loads fully coalesced+independent.
        const int total = gridDim.x * MAX_BINS;
        float s = 0.0f;
        for (int e = tid; e < total; e += TPB)
            s += g_partial[e];

        __shared__ float red[TPB];
        red[tid] = s;
        __syncthreads();

        if (tid < MAX_BINS) {
            float t = 0.0f;
            #pragma unroll
            for (int k = 0; k < TPB / MAX_BINS; k++)
                t += red[tid + k * MAX_BINS];
            red[tid] = fabsf(t);     // bins >= nb hold exact zeros
        }
        __syncthreads();

        if (tid == 0) {
            float tot = 0.0f;
            #pragma unroll
            for (int b = 0; b < MAX_BINS; b++)
                tot += red[b];
            out[0] = tot / (float)n;
            g_count = 0;             // reset for next graph replay
        }
    }
}

extern "C" void kernel_launch(void* const* d_in, const int* in_sizes, int n_in,
                              void* d_out, int out_size) {
    const float* conf = (const float*)d_in[0];
    const float* acc  = (const float*)d_in[1];
    const int*   nbp  = (const int*)d_in[2];
    float* out = (float*)d_out;
    const int n = in_sizes[0];

    int nvec = n >> 2;
    int blocks = (nvec + TPB - 1) / TPB;
    if (blocks > NBLOCKS) blocks = NBLOCKS;
    if (blocks < 1) blocks = 1;

    ece_kernel<<<blocks, TPB>>>(conf, acc, nbp, n, out);
}